// round 10
// baseline (speedup 1.0000x reference)
#include <cuda_runtime.h>
#include <cuda_bf16.h>

// RNN: h_t = tanh(h_{t-1} + x_t @ W1 + b1), out = sigmoid(h_63 @ W2 + b2)
// x: [B, 64, 16] f32, W1: [16,10], b1: [10], W2: [10,5], b2: [5], out: [B,5] f32
//
// Round 10: occupancy push. 4 lanes per batch = (K-half x unit-half); each
// lane holds 4 K-pair weights x 5 units = 40 regs (vs 80). Per-step cross-K
// combine via 5 shfl_xor. Warp = 8 batches; 1 cp.async(16B)/lane/step into an
// 8-slot ring (LOOKA=7, R7's proven schedule). launch_bounds(128,6) -> 24 warps/SM.

#define SEQ   64
#define INF   16
#define HID   10
#define OUTF  5
#define ROWF  (SEQ*INF)     // 1024 floats per batch
#define RST   20            // smem row stride in floats
#define BPW   8             // batches per warp
#define WPB   4             // warps per block
#define SLOT  (BPW*RST)     // 160 floats per ring slot
#define NSLOT 8             // ring slots
#define LOOKA 7             // cp.async lookahead

typedef unsigned long long u64;

__device__ __forceinline__ u64 pack2(float lo, float hi) {
    u64 r; asm("mov.b64 %0, {%1,%2};" : "=l"(r) : "f"(lo), "f"(hi)); return r;
}
__device__ __forceinline__ void unpack2(float& lo, float& hi, u64 v) {
    asm("mov.b64 {%0,%1}, %2;" : "=f"(lo), "=f"(hi) : "l"(v));
}
__device__ __forceinline__ u64 fma2(u64 a, u64 b, u64 c) {
    u64 d; asm("fma.rn.f32x2 %0, %1, %2, %3;" : "=l"(d) : "l"(a), "l"(b), "l"(c)); return d;
}
__device__ __forceinline__ float tanh_fast(float x) {
    float y; asm("tanh.approx.f32 %0, %1;" : "=f"(y) : "f"(x)); return y;
}
__device__ __forceinline__ float sigmoid_fast(float x) {
    float e; asm("ex2.approx.f32 %0, %1;" : "=f"(e) : "f"(x * -1.4426950408889634f));
    float r; asm("rcp.approx.f32 %0, %1;" : "=f"(r) : "f"(e + 1.0f));
    return r;
}

#define CP16(dst, src) \
    asm volatile("cp.async.cg.shared.global [%0], [%1], 16;" :: "r"(dst), "l"(src))
#define CPCOMMIT() asm volatile("cp.async.commit_group;")
#define CPWAIT(n)  asm volatile("cp.async.wait_group %0;" :: "n"(n))

__global__ void __launch_bounds__(WPB * 32, 6)
rnn_kernel(const float* __restrict__ x,
           const float* __restrict__ W1,
           const float* __restrict__ b1,
           const float* __restrict__ W2,
           const float* __restrict__ b2,
           float* __restrict__ out,
           int nbatch)
{
    __shared__ float buf[WPB][NSLOT * SLOT];   // 4 x 5 KB warp-private rings

    const int lane = threadIdx.x & 31;
    const int wid  = threadIdx.x >> 5;
    const int wbase = (blockIdx.x * WPB + wid) * BPW;
    if (wbase >= nbatch) return;

    const int sub = lane & 3;         // role within batch
    const int bl  = lane >> 2;        // batch-local 0..7
    const int kh  = sub & 1;          // K-half: inputs 8kh..8kh+7
    const int uh  = (sub >> 1) & 1;   // unit-half: units 5uh..5uh+4
    const int ub  = uh * 5;

    // ---- weights: 4 K-pairs x 5 units = 20 u64 = 40 regs ----
    u64 Wq[4][5];
#pragma unroll
    for (int ip = 0; ip < 4; ++ip)
#pragma unroll
        for (int j = 0; j < 5; ++j)
            Wq[ip][j] = pack2(__ldg(W1 + (8*kh + 2*ip)     * HID + ub + j),
                              __ldg(W1 + (8*kh + 2*ip + 1) * HID + ub + j));
    float b1v[5], hb[5];
#pragma unroll
    for (int j = 0; j < 5; ++j) { b1v[j] = __ldg(b1 + ub + j); hb[j] = b1v[j]; }

    // ---- producer: 1 x 16B chunk per lane per step ----
    const int prow = lane >> 2;       // batch row 0..7
    const int w    = lane & 3;        // 16B word within the 64B step row
    const float4* src = reinterpret_cast<const float4*>(
        x + (size_t)(wbase + prow) * ROWF) + w;
    float* sbf = &buf[wid][0];
    const unsigned sb32 = (unsigned)__cvta_generic_to_shared(sbf);
    const unsigned st0 = sb32 + (unsigned)((prow * RST + w * 4) << 2);

    // prologue: LOOKA step-groups in flight
#pragma unroll
    for (int k = 0; k < LOOKA; ++k) {
        CP16(st0 + (unsigned)(k & (NSLOT - 1)) * (SLOT * 4), src + 4 * k);
        CPCOMMIT();
    }

    const float* myrow = sbf + bl * RST + kh * 8;   // this lane's 8 inputs

#pragma unroll 2
    for (int s = 0; s < SEQ; ++s) {
        CPWAIT(LOOKA - 1);    // group s complete (this thread's chunk)
        __syncwarp();         // slot s readable; slot s-1 reads all done

        // refill: step s+LOOKA -> slot (s+LOOKA)&7 = (s-1)&7 (just freed)
        {
            const int f = s + LOOKA;
            if (f < SEQ)
                CP16(st0 + (unsigned)(f & (NSLOT - 1)) * (SLOT * 4), src + 4 * f);
            CPCOMMIT();       // empty tail group keeps wait-count exact
        }

        // compute: this lane's 8 inputs (2 LDS.128), 20 fma2
        const ulonglong2* rowq =
            reinterpret_cast<const ulonglong2*>(myrow + (s & (NSLOT - 1)) * SLOT);
        const ulonglong2 p0 = rowq[0];
        const ulonglong2 p1 = rowq[1];
        const u64 xq[4] = {p0.x, p0.y, p1.x, p1.y};

        u64 a0 = 0, a1 = 0, a2 = 0, a3 = 0, a4 = 0;
#pragma unroll
        for (int ip = 0; ip < 4; ++ip) {
            a0 = fma2(xq[ip], Wq[ip][0], a0);
            a1 = fma2(xq[ip], Wq[ip][1], a1);
            a2 = fma2(xq[ip], Wq[ip][2], a2);
            a3 = fma2(xq[ip], Wq[ip][3], a3);
            a4 = fma2(xq[ip], Wq[ip][4], a4);
        }

        // fold f32x2 lanes, combine K-halves (lane^1), tanh, carry hb
        const u64 aa[5] = {a0, a1, a2, a3, a4};
#pragma unroll
        for (int j = 0; j < 5; ++j) {
            float lo, hi; unpack2(lo, hi, aa[j]);
            float f = lo + hi;
            f += __shfl_xor_sync(0xffffffffu, f, 1);
            const float h = tanh_fast(hb[j] + f);
            hb[j] = h + b1v[j];
        }
    }

    // ---- epilogue: h = hb - b1; partial h@W2 per unit-half, combine (lane^2)
    float hv[5];
#pragma unroll
    for (int j = 0; j < 5; ++j) hv[j] = hb[j] - b1v[j];

    float po[OUTF];
#pragma unroll
    for (int o = 0; o < OUTF; ++o) {
        float a = 0.0f;
#pragma unroll
        for (int k = 0; k < 5; ++k)
            a = fmaf(hv[k], __ldg(W2 + (ub + k) * OUTF + o), a);
        po[o] = a + __shfl_xor_sync(0xffffffffu, a, 2);
    }
    if (sub == 0) {
        const long b = wbase + bl;
        if (b < nbatch) {
#pragma unroll
            for (int o = 0; o < OUTF; ++o)
                out[b * OUTF + o] = sigmoid_fast(po[o] + __ldg(b2 + o));
        }
    }
}

extern "C" void kernel_launch(void* const* d_in, const int* in_sizes, int n_in,
                              void* d_out, int out_size)
{
    const float* x  = (const float*)d_in[0];
    const float* W1 = (const float*)d_in[1];
    const float* b1 = (const float*)d_in[2];
    const float* W2 = (const float*)d_in[3];
    const float* b2 = (const float*)d_in[4];
    float* out = (float*)d_out;

    int nbatch = in_sizes[0] / ROWF;                       // 65536
    int blocks = (nbatch + WPB * BPW - 1) / (WPB * BPW);   // 2048
    rnn_kernel<<<blocks, WPB * 32>>>(x, W1, b1, W2, b2, out, nbatch);
}

// round 11
// speedup vs baseline: 1.1077x; 1.1077x over previous
#include <cuda_runtime.h>
#include <cuda_bf16.h>

// RNN: h_t = tanh(h_{t-1} + x_t @ W1 + b1), out = sigmoid(h_63 @ W2 + b2)
// x: [B, 64, 16] f32, W1: [16,10], b1: [10], W2: [10,5], b2: [5], out: [B,5] f32
//
// Round 11: exact R7 (best: K-pair FFMA2, 8-slot ring, LOOKA=7, grid 1024)
// with ONE change: cp.async carries .L2::256B prefetch, so DRAM is accessed
// in 256B bursts (one per 4 steps per batch-row) instead of random 64B
// granules; steps 4t+1..4t+3 become L2 hits. Traffic unchanged (L2 dedup).

#define SEQ   64
#define INF   16
#define HID   10
#define OUTF  5
#define ROWF  (SEQ*INF)     // 1024 floats per batch
#define RST   20            // smem row stride in floats (16B aligned)
#define BPW   16            // batches per warp
#define WPB   4             // warps per block
#define SLOT  (BPW*RST)     // 320 floats per ring slot
#define NSLOT 8             // ring slots
#define LOOKA 7             // cp.async lookahead (max = NSLOT-1)

typedef unsigned long long u64;

__device__ __forceinline__ u64 pack2(float lo, float hi) {
    u64 r; asm("mov.b64 %0, {%1,%2};" : "=l"(r) : "f"(lo), "f"(hi)); return r;
}
__device__ __forceinline__ void unpack2(float& lo, float& hi, u64 v) {
    asm("mov.b64 {%0,%1}, %2;" : "=f"(lo), "=f"(hi) : "l"(v));
}
__device__ __forceinline__ u64 fma2(u64 a, u64 b, u64 c) {
    u64 d; asm("fma.rn.f32x2 %0, %1, %2, %3;" : "=l"(d) : "l"(a), "l"(b), "l"(c)); return d;
}
__device__ __forceinline__ float tanh_fast(float x) {
    float y; asm("tanh.approx.f32 %0, %1;" : "=f"(y) : "f"(x)); return y;
}
__device__ __forceinline__ float sigmoid_fast(float x) {
    float e; asm("ex2.approx.f32 %0, %1;" : "=f"(e) : "f"(x * -1.4426950408889634f));
    float r; asm("rcp.approx.f32 %0, %1;" : "=f"(r) : "f"(e + 1.0f));
    return r;
}

// 16B async copy with 256B L2 prefetch: DRAM fetches the whole 256B region
// (4 consecutive steps of this batch row); later steps hit L2.
#define CP16(dst, src) \
    asm volatile("cp.async.cg.shared.global.L2::256B [%0], [%1], 16;" \
                 :: "r"(dst), "l"(src))
#define CPCOMMIT() asm volatile("cp.async.commit_group;")
#define CPWAIT(n)  asm volatile("cp.async.wait_group %0;" :: "n"(n))

__global__ void __launch_bounds__(WPB * 32, 4)
rnn_kernel(const float* __restrict__ x,
           const float* __restrict__ W1,
           const float* __restrict__ b1,
           const float* __restrict__ W2,
           const float* __restrict__ b2,
           float* __restrict__ out,
           int nbatch)
{
    __shared__ float buf[WPB][NSLOT * SLOT];   // 4 x 10 KB warp-private rings

    const int lane = threadIdx.x & 31;
    const int wid  = threadIdx.x >> 5;
    const int wbase = (blockIdx.x * WPB + wid) * BPW;
    if (wbase >= nbatch) return;

    const int half = lane & 1;        // which 5 hidden units
    const int bl   = lane >> 1;       // batch-local 0..15
    const int ub   = half * 5;        // first unit of this half

    // ---- weights, K-pair packed: Wq[ip][j] = (W1[2ip][ub+j], W1[2ip+1][ub+j])
    u64 Wq[8][5];
#pragma unroll
    for (int ip = 0; ip < 8; ++ip)
#pragma unroll
        for (int j = 0; j < 5; ++j)
            Wq[ip][j] = pack2(__ldg(W1 + (2*ip)*HID + ub + j),
                              __ldg(W1 + (2*ip+1)*HID + ub + j));
    float b1v[5], h[5], hb[5];
#pragma unroll
    for (int j = 0; j < 5; ++j) { b1v[j] = __ldg(b1 + ub + j); h[j] = 0.0f; hb[j] = b1v[j]; }

    // ---- producer addressing: 2 x 16B chunks per thread per step ----
    const float4* src0 = reinterpret_cast<const float4*>(
        x + (size_t)(wbase + (lane >> 2)) * ROWF) + (lane & 3);
    float* sbf = &buf[wid][0];
    const unsigned sb32 = (unsigned)__cvta_generic_to_shared(sbf);
    const unsigned st0 = sb32 + ((((lane >> 2)) * RST + (lane & 3) * 4) << 2);
    const unsigned D_ST = 8 * RST * 4;          // +8 batches in smem (bytes)

    // prologue: LOOKA steps in flight, one commit group each
#pragma unroll
    for (int k = 0; k < LOOKA; ++k) {
        const unsigned so = (unsigned)(k & (NSLOT - 1)) * (SLOT * 4);
        CP16(st0 + so,        src0 + 4 * k);
        CP16(st0 + so + D_ST, src0 + 4 * k + 2 * ROWF);   // +8 batches = 2*ROWF float4s
        CPCOMMIT();
    }

    const float* myrow = sbf + bl * RST;

#pragma unroll 2
    for (int s = 0; s < SEQ; ++s) {
        CPWAIT(LOOKA - 1);    // group s complete (this thread's chunks)
        __syncwarp();         // all lanes past wait -> slot s readable,
                              // and all lanes' reads of slot s-1 are done

        // keep pipeline full: step s+LOOKA -> slot (s+LOOKA)&7 = (s-1)&7
        {
            const int f = s + LOOKA;
            if (f < SEQ) {
                const unsigned so = (unsigned)(f & (NSLOT - 1)) * (SLOT * 4);
                CP16(st0 + so,        src0 + 4 * f);
                CP16(st0 + so + D_ST, src0 + 4 * f + 2 * ROWF);
            }
            CPCOMMIT();       // empty tail group keeps wait-count exact
        }

        // compute step s: x-pairs straight from LDS.128
        const ulonglong2* rowq =
            reinterpret_cast<const ulonglong2*>(myrow + (s & (NSLOT - 1)) * SLOT);
        u64 a0 = 0, a1 = 0, a2 = 0, a3 = 0, a4 = 0;

        {   // inputs 0..7
            const ulonglong2 p0 = rowq[0];
            const ulonglong2 p1 = rowq[1];
            const u64 xq[4] = {p0.x, p0.y, p1.x, p1.y};
#pragma unroll
            for (int ip = 0; ip < 4; ++ip) {
                a0 = fma2(xq[ip], Wq[ip][0], a0);
                a1 = fma2(xq[ip], Wq[ip][1], a1);
                a2 = fma2(xq[ip], Wq[ip][2], a2);
                a3 = fma2(xq[ip], Wq[ip][3], a3);
                a4 = fma2(xq[ip], Wq[ip][4], a4);
            }
        }
        {   // inputs 8..15
            const ulonglong2 p2 = rowq[2];
            const ulonglong2 p3 = rowq[3];
            const u64 xq[4] = {p2.x, p2.y, p3.x, p3.y};
#pragma unroll
            for (int ip = 0; ip < 4; ++ip) {
                a0 = fma2(xq[ip], Wq[4 + ip][0], a0);
                a1 = fma2(xq[ip], Wq[4 + ip][1], a1);
                a2 = fma2(xq[ip], Wq[4 + ip][2], a2);
                a3 = fma2(xq[ip], Wq[4 + ip][3], a3);
                a4 = fma2(xq[ip], Wq[4 + ip][4], a4);
            }
        }

        u64 aa[5] = {a0, a1, a2, a3, a4};
#pragma unroll
        for (int j = 0; j < 5; ++j) {
            float lo, hi; unpack2(lo, hi, aa[j]);
            h[j]  = tanh_fast(hb[j] + (lo + hi));
            hb[j] = h[j] + b1v[j];
        }
    }

    // ---- epilogue: partial h@W2 per half, combine via shfl ----
    float po[OUTF];
#pragma unroll
    for (int o = 0; o < OUTF; ++o) {
        float a = 0.0f;
#pragma unroll
        for (int k = 0; k < 5; ++k)
            a = fmaf(h[k], __ldg(W2 + (ub + k) * OUTF + o), a);
        po[o] = a + __shfl_xor_sync(0xffffffffu, a, 1);
    }
    if (half == 0) {
        const long b = wbase + bl;
        if (b < nbatch) {
#pragma unroll
            for (int o = 0; o < OUTF; ++o)
                out[b * OUTF + o] = sigmoid_fast(po[o] + __ldg(b2 + o));
        }
    }
}

extern "C" void kernel_launch(void* const* d_in, const int* in_sizes, int n_in,
                              void* d_out, int out_size)
{
    const float* x  = (const float*)d_in[0];
    const float* W1 = (const float*)d_in[1];
    const float* b1 = (const float*)d_in[2];
    const float* W2 = (const float*)d_in[3];
    const float* b2 = (const float*)d_in[4];
    float* out = (float*)d_out;

    int nbatch = in_sizes[0] / ROWF;                       // 65536
    int blocks = (nbatch + WPB * BPW - 1) / (WPB * BPW);   // 1024
    rnn_kernel<<<blocks, WPB * 32>>>(x, W1, b1, W2, b2, out, nbatch);
}